// round 4
// baseline (speedup 1.0000x reference)
#include <cuda_runtime.h>
#include <cstdint>

// Problem constants
#define BB   16
#define CC   128
#define C4C  32
#define NPIX 2304                      // H*W = 48*48
#define NT   18                        // NPIX / 128
#define PB   (NT*NT)                   // KQ tile-blocks per batch = 324
#define BN_EPS 1e-5f

static const size_t N2 = (size_t)NPIX * (size_t)NPIX;

// -------- scratch (device globals; no allocation allowed) --------
__device__ float g_K [BB * C4C * NPIX];
__device__ float g_Q [BB * C4C * NPIX];
__device__ float g_V [BB * CC  * NPIX];
__device__ float g_KQ[(size_t)BB * (size_t)NPIX * (size_t)NPIX]; // 340 MB
__device__ float g_pm[BB * PB];
__device__ float g_pZ[BB * NT];
__device__ float g_M [BB];

// -------- packed f32x2 helpers (Blackwell PTX, family-portable) --------
__device__ __forceinline__ unsigned long long pk2(float lo, float hi) {
    unsigned long long r;
    asm("mov.b64 %0, {%1,%2};" : "=l"(r) : "f"(lo), "f"(hi));
    return r;
}
__device__ __forceinline__ float2 up2(unsigned long long v) {
    float2 r;
    asm("mov.b64 {%0,%1}, %2;" : "=f"(r.x), "=f"(r.y) : "l"(v));
    return r;
}
__device__ __forceinline__ void fma2(unsigned long long& d,
                                     unsigned long long a,
                                     unsigned long long b) {
    asm("fma.rn.f32x2 %0, %1, %2, %0;" : "+l"(d) : "l"(a), "l"(b));
}

__device__ __forceinline__ uint32_t smem_to_u32(const void* p) {
    uint32_t a;
    asm("{ .reg .u64 t; cvta.to.shared.u64 t, %1; cvt.u32.u64 %0, t; }"
        : "=r"(a) : "l"(p));
    return a;
}
__device__ __forceinline__ float tf32r(float x) {
    uint32_t u;
    asm("cvt.rna.tf32.f32 %0, %1;" : "=r"(u) : "f"(x));
    return __uint_as_float(u);
}
__device__ __forceinline__ void cp16(uint32_t dst, const void* src) {
    asm volatile("cp.async.cg.shared.global [%0], [%1], 16;"
                 :: "r"(dst), "l"(src) : "memory");
}
#define CP_COMMIT() asm volatile("cp.async.commit_group;" ::: "memory")
#define CP_WAIT0()  asm volatile("cp.async.wait_group 0;" ::: "memory")

// warp-level tf32 MMA (family-portable, sm_80+): D[16x8] += A[16x8] * B[8x8]
__device__ __forceinline__ void mma16n8k8(float* d, const uint32_t* a,
                                          const uint32_t* b) {
    asm volatile(
        "mma.sync.aligned.m16n8k8.row.col.f32.tf32.tf32.f32 "
        "{%0,%1,%2,%3}, {%4,%5,%6,%7}, {%8,%9}, {%0,%1,%2,%3};"
        : "+f"(d[0]), "+f"(d[1]), "+f"(d[2]), "+f"(d[3])
        : "r"(a[0]), "r"(a[1]), "r"(a[2]), "r"(a[3]), "r"(b[0]), "r"(b[1]));
}

// ============================================================================
// conv128: Y[b,o,n] = relu( sum_c Wf[o,c]*X[b,c,n] + bias[o] ),  O = 128
// ============================================================================
__global__ void __launch_bounds__(256) conv128_kernel(
    const float* __restrict__ X, size_t xStride, int CIN,
    const float* __restrict__ W,
    const float* __restrict__ gam, const float* __restrict__ bet,
    const float* __restrict__ mean, const float* __restrict__ var,
    float* __restrict__ Y, size_t yStride)
{
    __shared__ __align__(16) float Ws[16][128];
    __shared__ __align__(16) float Xs[16][128];
    __shared__ float scale_s[128], bias_s[128];

    const int t  = threadIdx.x;
    const int b  = blockIdx.y;
    const int n0 = blockIdx.x * 128;

    if (t < 128) {
        float s = gam[t] * rsqrtf(var[t] + BN_EPS);
        scale_s[t] = s;
        bias_s[t]  = bet[t] - mean[t] * s;
    }
    __syncthreads();

    const float* Xb = X + (size_t)b * xStride + n0;
    const int ty = t >> 4, tx = t & 15;

    unsigned long long acc[8][4];
#pragma unroll
    for (int i = 0; i < 8; i++)
#pragma unroll
        for (int j = 0; j < 4; j++) acc[i][j] = 0ull;

    for (int c0 = 0; c0 < CIN; c0 += 16) {
#pragma unroll
        for (int i = t; i < 2048; i += 256) {
            int k = i >> 7, o = i & 127;
            Ws[k][o] = W[o * CIN + c0 + k] * scale_s[o];
        }
#pragma unroll
        for (int i = t; i < 2048; i += 256) {
            int k = i >> 7, n = i & 127;
            Xs[k][n] = Xb[(size_t)(c0 + k) * NPIX + n];
        }
        __syncthreads();

#pragma unroll 4
        for (int k = 0; k < 16; k++) {
            float4 a0 = *(const float4*)&Ws[k][ty * 8];
            float4 a1 = *(const float4*)&Ws[k][ty * 8 + 4];
            unsigned long long ad[8] = {
                pk2(a0.x, a0.x), pk2(a0.y, a0.y), pk2(a0.z, a0.z), pk2(a0.w, a0.w),
                pk2(a1.x, a1.x), pk2(a1.y, a1.y), pk2(a1.z, a1.z), pk2(a1.w, a1.w)};
            unsigned long long bv[4];
#pragma unroll
            for (int j = 0; j < 4; j++)
                bv[j] = *(const unsigned long long*)&Xs[k][tx * 8 + 2 * j];
#pragma unroll
            for (int i = 0; i < 8; i++)
#pragma unroll
                for (int j = 0; j < 4; j++) fma2(acc[i][j], ad[i], bv[j]);
        }
        __syncthreads();
    }

    float* Yb = Y + (size_t)b * yStride + n0 + tx * 8;
#pragma unroll
    for (int i = 0; i < 8; i++) {
        int o = ty * 8 + i;
        float bi = bias_s[o];
        float2 p0 = up2(acc[i][0]), p1 = up2(acc[i][1]);
        float2 p2 = up2(acc[i][2]), p3 = up2(acc[i][3]);
        float4 r0 = make_float4(fmaxf(p0.x + bi, 0.f), fmaxf(p0.y + bi, 0.f),
                                fmaxf(p1.x + bi, 0.f), fmaxf(p1.y + bi, 0.f));
        float4 r1 = make_float4(fmaxf(p2.x + bi, 0.f), fmaxf(p2.y + bi, 0.f),
                                fmaxf(p3.x + bi, 0.f), fmaxf(p3.y + bi, 0.f));
        *(float4*)&Yb[(size_t)o * NPIX]     = r0;
        *(float4*)&Yb[(size_t)o * NPIX + 4] = r1;
    }
}

// ============================================================================
// conv_kq: K/Q = relu(BN(w_kq @ x_en/x_de)),  O = 32, CIN = 128
// ============================================================================
__global__ void __launch_bounds__(256) conv_kq_kernel(
    const float* __restrict__ Xen, const float* __restrict__ Xde,
    const float* __restrict__ W,
    const float* __restrict__ gam, const float* __restrict__ bet,
    const float* __restrict__ mean, const float* __restrict__ var)
{
    __shared__ __align__(16) float Ws[16][32];
    __shared__ __align__(16) float Xs[16][128];
    __shared__ float scale_s[32], bias_s[32];

    const int t  = threadIdx.x;
    const int b  = blockIdx.y;
    const int n0 = blockIdx.x * 128;
    const float* X = (blockIdx.z == 0) ? Xen : Xde;
    float* Y       = (blockIdx.z == 0) ? g_K : g_Q;

    if (t < 32) {
        float s = gam[t] * rsqrtf(var[t] + BN_EPS);
        scale_s[t] = s;
        bias_s[t]  = bet[t] - mean[t] * s;
    }
    __syncthreads();

    const float* Xb = X + (size_t)b * CC * NPIX + n0;
    const int ty = t >> 4, tx = t & 15;

    unsigned long long acc[2][4];
#pragma unroll
    for (int i = 0; i < 2; i++)
#pragma unroll
        for (int j = 0; j < 4; j++) acc[i][j] = 0ull;

    for (int c0 = 0; c0 < CC; c0 += 16) {
#pragma unroll
        for (int i = t; i < 512; i += 256) {
            int k = i >> 5, o = i & 31;
            Ws[k][o] = W[o * CC + c0 + k] * scale_s[o];
        }
#pragma unroll
        for (int i = t; i < 2048; i += 256) {
            int k = i >> 7, n = i & 127;
            Xs[k][n] = Xb[(size_t)(c0 + k) * NPIX + n];
        }
        __syncthreads();

#pragma unroll 4
        for (int k = 0; k < 16; k++) {
            float2 a = *(const float2*)&Ws[k][ty * 2];
            unsigned long long a0 = pk2(a.x, a.x);
            unsigned long long a1 = pk2(a.y, a.y);
            unsigned long long bv[4];
#pragma unroll
            for (int j = 0; j < 4; j++)
                bv[j] = *(const unsigned long long*)&Xs[k][tx * 8 + 2 * j];
#pragma unroll
            for (int j = 0; j < 4; j++) { fma2(acc[0][j], a0, bv[j]); fma2(acc[1][j], a1, bv[j]); }
        }
        __syncthreads();
    }

    float* Yb = Y + (size_t)b * C4C * NPIX + n0 + tx * 8;
#pragma unroll
    for (int i = 0; i < 2; i++) {
        int o = ty * 2 + i;
        float bi = bias_s[o];
        float2 p0 = up2(acc[i][0]), p1 = up2(acc[i][1]);
        float2 p2 = up2(acc[i][2]), p3 = up2(acc[i][3]);
        float4 r0 = make_float4(fmaxf(p0.x + bi, 0.f), fmaxf(p0.y + bi, 0.f),
                                fmaxf(p1.x + bi, 0.f), fmaxf(p1.y + bi, 0.f));
        float4 r1 = make_float4(fmaxf(p2.x + bi, 0.f), fmaxf(p2.y + bi, 0.f),
                                fmaxf(p3.x + bi, 0.f), fmaxf(p3.y + bi, 0.f));
        *(float4*)&Yb[(size_t)o * NPIX]     = r0;
        *(float4*)&Yb[(size_t)o * NPIX + 4] = r1;
    }
}

// ============================================================================
// kqgemm: KQ[b,n,m] = sum_k K[b,k,n]*Q[b,k,m]  (k depth = 32), fp32 SIMT.
// Stores raw KQ (streaming) + per-block MAX only (Z is computed in feat).
// ============================================================================
__global__ void __launch_bounds__(256) kqgemm_kernel()
{
    __shared__ __align__(16) float Ks[32][128];
    __shared__ __align__(16) float Qs[32][128];

    const int t  = threadIdx.x;
    const int b  = blockIdx.z;
    const int n0 = blockIdx.y * 128;
    const int m0 = blockIdx.x * 128;

    const float* Kb = g_K + (size_t)b * C4C * NPIX;
    const float* Qb = g_Q + (size_t)b * C4C * NPIX;

#pragma unroll
    for (int i = t; i < 4096; i += 256) {
        int k = i >> 7, c = i & 127;
        Ks[k][c] = Kb[(size_t)k * NPIX + n0 + c];
        Qs[k][c] = Qb[(size_t)k * NPIX + m0 + c];
    }
    __syncthreads();

    const int ty = t >> 4, tx = t & 15;
    unsigned long long acc[8][4];
#pragma unroll
    for (int i = 0; i < 8; i++)
#pragma unroll
        for (int j = 0; j < 4; j++) acc[i][j] = 0ull;

#pragma unroll 4
    for (int k = 0; k < 32; k++) {
        float4 a0 = *(const float4*)&Ks[k][ty * 8];
        float4 a1 = *(const float4*)&Ks[k][ty * 8 + 4];
        unsigned long long ad[8] = {
            pk2(a0.x, a0.x), pk2(a0.y, a0.y), pk2(a0.z, a0.z), pk2(a0.w, a0.w),
            pk2(a1.x, a1.x), pk2(a1.y, a1.y), pk2(a1.z, a1.z), pk2(a1.w, a1.w)};
        unsigned long long bv[4];
#pragma unroll
        for (int j = 0; j < 4; j++)
            bv[j] = *(const unsigned long long*)&Qs[k][tx * 8 + 2 * j];
#pragma unroll
        for (int i = 0; i < 8; i++)
#pragma unroll
            for (int j = 0; j < 4; j++) fma2(acc[i][j], ad[i], bv[j]);
    }

    float vmax = -1e30f;
#pragma unroll
    for (int i = 0; i < 8; i++) {
        float vals[8];
#pragma unroll
        for (int j = 0; j < 4; j++) {
            float2 p = up2(acc[i][j]);
            vals[2 * j]     = p.x;
            vals[2 * j + 1] = p.y;
            vmax = fmaxf(vmax, fmaxf(p.x, p.y));
        }
        size_t off = (size_t)b * N2 + (size_t)(n0 + ty * 8 + i) * NPIX + m0 + tx * 8;
        __stcs((float4*)&g_KQ[off],
               make_float4(vals[0], vals[1], vals[2], vals[3]));
        __stcs((float4*)&g_KQ[off + 4],
               make_float4(vals[4], vals[5], vals[6], vals[7]));
    }

    __syncthreads();
    float* sm = (float*)Ks;
    sm[t] = vmax;
    __syncthreads();
    for (int s = 128; s > 0; s >>= 1) {
        if (t < s) sm[t] = fmaxf(sm[t], sm[t + s]);
        __syncthreads();
    }
    if (t == 0) g_pm[b * PB + blockIdx.y * NT + blockIdx.x] = sm[0];
}

// ============================================================================
// combine: reduce PB max partials -> per-batch M.
// ============================================================================
__global__ void __launch_bounds__(512) combine_kernel()
{
    __shared__ float sm[512];
    const int b = blockIdx.x, t = threadIdx.x;
    sm[t] = (t < PB) ? g_pm[b * PB + t] : -INFINITY;
    __syncthreads();
    for (int s = 256; s > 0; s >>= 1) {
        if (t < s) sm[t] = fmaxf(sm[t], sm[t + s]);
        __syncthreads();
    }
    if (t == 0) g_M[b] = sm[0];
}

// ============================================================================
// feat_mma: feat_unnorm[b,c,n] = sum_m V[b,c,m] * exp(KQ[b,n,m] - M)
// via warp-level mma.sync m16n8k8 tf32 (family-portable tensor path).
// Block = 128(c) x 128(n), K(m) chunks of 32. cp.async raw staging,
// producer does exp + tf32-round into XOR-swizzled K-major tiles.
// Also emits per-block sum(P) partial -> g_pZ (Z finalized in scale kernel).
// grid: (NT, B), 256 threads.
// ============================================================================
// dynamic smem (floats): VsSw[128*32] | PsSw[128*32] | rawV[128*36] | rawK[128*36]
#define FM_SMEM_FLOATS (4096 + 4096 + 4608 + 4608)
#define FM_SMEM_BYTES  (FM_SMEM_FLOATS * 4)

__global__ void __launch_bounds__(256, 2) feat_mma_kernel(float* __restrict__ out)
{
    extern __shared__ __align__(16) float fsm[];
    float* VsSw = fsm;
    float* PsSw = fsm + 4096;
    float* rawV = fsm + 8192;
    float* rawK = fsm + 12800;
    __shared__ float zred[256];

    const int t    = threadIdx.x;
    const int b    = blockIdx.y;
    const int n0   = blockIdx.x * 128;
    const float Mb = g_M[b];

    const int lane = t & 31, wid = t >> 5;
    const int wc = wid >> 1, wn = wid & 1;      // 4 x 2 warp grid
    const int g = lane >> 2, c4 = lane & 3;

    // producer mapping: thread handles row r (V-channel c=r AND KQ-row n=r), half h
    const int r = t >> 1, h = t & 1;
    const float* Vrow = g_V  + (size_t)b * CC * NPIX + (size_t)r * NPIX + h * 16;
    const float* Krow = g_KQ + (size_t)b * N2 + (size_t)(n0 + r) * NPIX + h * 16;
    const uint32_t rawVa = smem_to_u32(rawV) + (uint32_t)(r * 36 + h * 16) * 4;
    const uint32_t rawKa = smem_to_u32(rawK) + (uint32_t)(r * 36 + h * 16) * 4;

    // issue chunk 0
#pragma unroll
    for (int q = 0; q < 4; q++) {
        cp16(rawVa + q * 16, Vrow + q * 4);
        cp16(rawKa + q * 16, Krow + q * 4);
    }
    CP_COMMIT();

    float acc[2][8][4];
#pragma unroll
    for (int mt = 0; mt < 2; mt++)
#pragma unroll
        for (int nt = 0; nt < 8; nt++)
#pragma unroll
            for (int j = 0; j < 4; j++) acc[mt][nt][j] = 0.f;
    float zacc = 0.f;

    for (int i = 0; i < 72; i++) {
        CP_WAIT0();
        __syncthreads();                 // raw ready; swizzled tiles consumed

        // transform: raw -> tf32 swizzled tiles; exp for P; accumulate Z
#pragma unroll
        for (int j = 0; j < 16; j++) {
            int m  = h * 16 + j;
            int sw = m ^ ((r & 7) << 2);
            VsSw[r * 32 + sw] = tf32r(rawV[r * 36 + m]);
            float p = __expf(rawK[r * 36 + m] - Mb);
            zacc += p;
            PsSw[r * 32 + sw] = tf32r(p);
        }
        __syncthreads();                 // tiles ready; raw free

        if (i < 71) {
            const float* Vp = Vrow + (i + 1) * 32;
            const float* Kp = Krow + (i + 1) * 32;
#pragma unroll
            for (int q = 0; q < 4; q++) {
                cp16(rawVa + q * 16, Vp + q * 4);
                cp16(rawKa + q * 16, Kp + q * 4);
            }
            CP_COMMIT();
        }

        // consume: 4 k-steps of 8
#pragma unroll
        for (int ks = 0; ks < 4; ks++) {
            const int k0 = ks * 8;
            uint32_t a[2][4], bf[8][2];
#pragma unroll
            for (int mt = 0; mt < 2; mt++) {
                int r0 = wc * 32 + mt * 16 + g;
                int r1 = r0 + 8;
                a[mt][0] = __float_as_uint(VsSw[r0 * 32 + ((k0 + c4)     ^ ((r0 & 7) << 2))]);
                a[mt][1] = __float_as_uint(VsSw[r1 * 32 + ((k0 + c4)     ^ ((r1 & 7) << 2))]);
                a[mt][2] = __float_as_uint(VsSw[r0 * 32 + ((k0 + 4 + c4) ^ ((r0 & 7) << 2))]);
                a[mt][3] = __float_as_uint(VsSw[r1 * 32 + ((k0 + 4 + c4) ^ ((r1 & 7) << 2))]);
            }
#pragma unroll
            for (int nt = 0; nt < 8; nt++) {
                int nr = wn * 64 + nt * 8 + g;
                bf[nt][0] = __float_as_uint(PsSw[nr * 32 + ((k0 + c4)     ^ ((nr & 7) << 2))]);
                bf[nt][1] = __float_as_uint(PsSw[nr * 32 + ((k0 + 4 + c4) ^ ((nr & 7) << 2))]);
            }
#pragma unroll
            for (int mt = 0; mt < 2; mt++)
#pragma unroll
                for (int nt = 0; nt < 8; nt++)
                    mma16n8k8(acc[mt][nt], a[mt], bf[nt]);
        }
    }

    // per-block sum(P) partial
    zred[t] = zacc;
    __syncthreads();
    for (int s = 128; s > 0; s >>= 1) {
        if (t < s) zred[t] += zred[t + s];
        __syncthreads();
    }
    if (t == 0) g_pZ[b * NT + blockIdx.x] = zred[0];

    // store unnormalized feat (scale kernel divides by Z)
    float* Ob = out + (size_t)b * (2 * CC) * NPIX + (size_t)CC * NPIX + n0;
#pragma unroll
    for (int mt = 0; mt < 2; mt++) {
        int row0 = wc * 32 + mt * 16 + g;
#pragma unroll
        for (int nt = 0; nt < 8; nt++) {
            int col = wn * 64 + nt * 8 + 2 * c4;
            *(float2*)&Ob[(size_t)row0 * NPIX + col] =
                make_float2(acc[mt][nt][0], acc[mt][nt][1]);
            *(float2*)&Ob[(size_t)(row0 + 8) * NPIX + col] =
                make_float2(acc[mt][nt][2], acc[mt][nt][3]);
        }
    }
}

// ============================================================================
// scale: Z[b] = sum of NT partials; out feat half *= 1/Z.  grid (NT, B).
// ============================================================================
__global__ void __launch_bounds__(256) scale_kernel(float* __restrict__ out)
{
    __shared__ float zinv;
    const int t  = threadIdx.x;
    const int b  = blockIdx.y;
    const int n0 = blockIdx.x * 128;
    if (t == 0) {
        float z = 0.f;
#pragma unroll
        for (int j = 0; j < NT; j++) z += g_pZ[b * NT + j];
        zinv = 1.f / z;
    }
    __syncthreads();
    const float inv = zinv;

    const int c = t >> 1, h = t & 1;
    float* O = out + (size_t)b * (2 * CC) * NPIX + (size_t)(CC + c) * NPIX
                   + n0 + h * 64;
#pragma unroll
    for (int q = 0; q < 16; q++) {
        float4 v = *(float4*)&O[q * 4];
        v.x *= inv; v.y *= inv; v.z *= inv; v.w *= inv;
        *(float4*)&O[q * 4] = v;
    }
}

// ============================================================================
// launch
// ============================================================================
extern "C" void kernel_launch(void* const* d_in, const int* in_sizes, int n_in,
                              void* d_out, int out_size)
{
    const float* x_en   = (const float*)d_in[0];
    const float* x_de   = (const float*)d_in[1];
    const float* x_cat  = (const float*)d_in[2];
    const float* w_kq   = (const float*)d_in[3];
    const float* kq_g   = (const float*)d_in[4];
    const float* kq_b   = (const float*)d_in[5];
    const float* kq_m   = (const float*)d_in[6];
    const float* kq_v   = (const float*)d_in[7];
    const float* w_v    = (const float*)d_in[8];
    const float* v_g    = (const float*)d_in[9];
    const float* v_b    = (const float*)d_in[10];
    const float* v_m    = (const float*)d_in[11];
    const float* v_v    = (const float*)d_in[12];
    const float* w_red  = (const float*)d_in[13];
    const float* red_g  = (const float*)d_in[14];
    const float* red_b  = (const float*)d_in[15];
    const float* red_m  = (const float*)d_in[16];
    const float* red_v  = (const float*)d_in[17];
    float* out = (float*)d_out;

    float* pV = nullptr;
    cudaGetSymbolAddress((void**)&pV, g_V);

    cudaFuncSetAttribute(feat_mma_kernel,
                         cudaFuncAttributeMaxDynamicSharedMemorySize, FM_SMEM_BYTES);

    const size_t twoCN = (size_t)2 * CC * NPIX;
    const size_t CN    = (size_t)CC * NPIX;

    // x = relu(BN(w_red @ x_cat)) -> output channels [0, C)
    conv128_kernel<<<dim3(NT, BB), 256>>>(x_cat, twoCN, 2 * CC, w_red,
                                          red_g, red_b, red_m, red_v,
                                          out, twoCN);
    // V = relu(BN(w_v @ x))
    conv128_kernel<<<dim3(NT, BB), 256>>>(out, twoCN, CC, w_v,
                                          v_g, v_b, v_m, v_v,
                                          pV, CN);
    // K, Q
    conv_kq_kernel<<<dim3(NT, BB, 2), 256>>>(x_en, x_de, w_kq,
                                             kq_g, kq_b, kq_m, kq_v);
    // KQ + per-block max partials
    kqgemm_kernel<<<dim3(NT, NT, BB), 256>>>();
    // per-batch M (global max)
    combine_kernel<<<BB, 512>>>();
    // feat (tensor cores via mma.sync tf32) + Z partials
    feat_mma_kernel<<<dim3(NT, BB), 256, FM_SMEM_BYTES>>>(out);
    // normalize feat half by 1/Z
    scale_kernel<<<dim3(NT, BB), 256>>>(out);
}